// round 1
// baseline (speedup 1.0000x reference)
#include <cuda_runtime.h>

// Embedder: multirate zero-insert upsample -> conv1d(1->256, K=5, same) -> gather
// collapses to closed-form per-stream FIR taps. Output = [3,256,60000] X ++ [2,60000] S,
// all float32, 46,200,000 elements (~185 MB). Pure HBM-store-bound kernel.

#define L250   15000
#define L500   30000
#define L1000  60000
#define DMODEL 256
#define ROW4   (L1000 / 4)                  // 15000 float4 per (stream,d) row
#define X4TOT  (3 * DMODEL * ROW4)          // 11,520,000 float4
#define S4TOT  (2 * L1000 / 4)              // 30,000 float4
#define N4TOT  (X4TOT + S4TOT)              // 11,550,000 float4

__device__ __forceinline__ float ldx(const float* __restrict__ x, int i, int l) {
    return (i >= 0 && i < l) ? __ldg(x + i) : 0.0f;
}

__global__ void __launch_bounds__(256)
embedder_kernel(const float* __restrict__ x250,
                const float* __restrict__ x500,
                const float* __restrict__ x1000,
                const float* __restrict__ W,   // [256,1,5]
                const float* __restrict__ b,   // [256]
                float4* __restrict__ out,
                int n4)
{
    int i4 = blockIdx.x * blockDim.x + threadIdx.x;
    if (i4 >= n4) return;

    float4 o;

    if (i4 < X4TOT) {
        int row    = i4 / ROW4;                // 0..767  (= stream*256 + d)
        int p      = (i4 - row * ROW4) * 4;    // element position within L1000
        int stream = row / DMODEL;
        int d      = row - stream * DMODEL;

        if (stream == 0) {
            // only tap k=2 lands on a real sample (stride 4)
            if (p < L250) {
                float w2 = __ldg(W + d * 5 + 2);
                float bb = __ldg(b + d);
                o.x = fmaf(w2, __ldg(x250 + p + 0), bb);
                o.y = fmaf(w2, __ldg(x250 + p + 1), bb);
                o.z = fmaf(w2, __ldg(x250 + p + 2), bb);
                o.w = fmaf(w2, __ldg(x250 + p + 3), bb);
            } else {
                o = make_float4(0.f, 0.f, 0.f, 0.f);
            }
        } else if (stream == 1) {
            // taps k=0,2,4 land on real samples (stride 2)
            if (p < L500) {
                float w0 = __ldg(W + d * 5 + 0);
                float w2 = __ldg(W + d * 5 + 2);
                float w4 = __ldg(W + d * 5 + 4);
                float bb = __ldg(b + d);
                float v[6];
                #pragma unroll
                for (int t = 0; t < 6; t++) v[t] = ldx(x500, p - 1 + t, L500);
                float* po = (float*)&o;
                #pragma unroll
                for (int t = 0; t < 4; t++)
                    po[t] = fmaf(w0, v[t], fmaf(w2, v[t + 1], fmaf(w4, v[t + 2], bb)));
            } else {
                o = make_float4(0.f, 0.f, 0.f, 0.f);
            }
        } else {
            // stride 1: full 5-tap correlation, zero padding at both ends
            float w0 = __ldg(W + d * 5 + 0);
            float w1 = __ldg(W + d * 5 + 1);
            float w2 = __ldg(W + d * 5 + 2);
            float w3 = __ldg(W + d * 5 + 3);
            float w4 = __ldg(W + d * 5 + 4);
            float bb = __ldg(b + d);
            float v[8];
            #pragma unroll
            for (int t = 0; t < 8; t++) v[t] = ldx(x1000, p - 2 + t, L1000);
            float* po = (float*)&o;
            #pragma unroll
            for (int t = 0; t < 4; t++)
                po[t] = fmaf(w0, v[t],
                        fmaf(w1, v[t + 1],
                        fmaf(w2, v[t + 2],
                        fmaf(w3, v[t + 3],
                        fmaf(w4, v[t + 4], bb)))));
        }
    } else {
        // S = [rows(60000), cols(60000)] as float. Concatenated lengths
        // 15000/30000/60000 truncated to 60000 entries.
        int e = (i4 - X4TOT) * 4;
        float* po = (float*)&o;
        if (e < L1000) {
            // rows: band-constant; bands at 15000 / 45000 are float4-aligned
            float r = (e < L250) ? 0.f : ((e < L250 + L500) ? 1.f : 2.f);
            o = make_float4(r, r, r, r);
        } else {
            int p = e - L1000;
            #pragma unroll
            for (int t = 0; t < 4; t++) {
                int q = p + t;
                float c;
                if (q < L250)             c = (float)(q * 4);
                else if (q < L250 + L500) c = (float)((q - L250) * 2);
                else                      c = (float)(q - (L250 + L500));
                po[t] = c;
            }
        }
    }

    out[i4] = o;
}

extern "C" void kernel_launch(void* const* d_in, const int* in_sizes, int n_in,
                              void* d_out, int out_size) {
    const float* x250  = (const float*)d_in[0];
    const float* x500  = (const float*)d_in[1];
    const float* x1000 = (const float*)d_in[2];
    const float* W     = (const float*)d_in[3];
    const float* b     = (const float*)d_in[4];
    float4* out = (float4*)d_out;

    int n4 = out_size / 4;
    if (n4 > N4TOT) n4 = N4TOT;

    int threads = 256;
    int blocks = (n4 + threads - 1) / threads;
    embedder_kernel<<<blocks, threads>>>(x250, x500, x1000, W, b, out, n4);
}